// round 3
// baseline (speedup 1.0000x reference)
#include <cuda_runtime.h>
#include <cuda_fp16.h>
#include <cstdint>

#define BATCH 8192
#define IND   1024
#define OUTD  1024
#define DD    8
#define TM    128
#define TN    128
#define KC    64
#define NIC   16          // IND / KC
#define NSTEPS 128        // NIC * DD

// dynamic SMEM layout
#define SM_B     0        // double-buffered B tile: 2 x 16384
#define SM_BIAS  32768    // 8 x 128 f32 = 4096
#define SM_ALLOC 36864    // fits default 48KB limit, no attribute call needed

// fp16 copy of weights, [D][OUT][IN] row-major (K-major rows of 1024 halves)
__device__ __half g_wh[(size_t)DD * OUTD * IND];

static __device__ __forceinline__ uint32_t smem_u32(const void* p) {
    uint32_t a;
    asm("{ .reg .u64 t; cvta.to.shared.u64 t, %1; cvt.u32.u64 %0, t; }" : "=r"(a) : "l"(p));
    return a;
}
static __device__ __forceinline__ void cp16(uint32_t dst, const void* src) {
    asm volatile("cp.async.cg.shared.global [%0], [%1], 16;" :: "r"(dst), "l"(src));
}
static __device__ __forceinline__ void cp_commit() {
    asm volatile("cp.async.commit_group;" ::: "memory");
}
static __device__ __forceinline__ void cp_wait1() {
    asm volatile("cp.async.wait_group 1;" ::: "memory");
}
static __device__ __forceinline__ void cp_wait0() {
    asm volatile("cp.async.wait_group 0;" ::: "memory");
}
static __device__ __forceinline__ void ldsm4(uint32_t* r, uint32_t addr) {
    asm volatile("ldmatrix.sync.aligned.m8n8.x4.shared.b16 {%0,%1,%2,%3}, [%4];"
                 : "=r"(r[0]), "=r"(r[1]), "=r"(r[2]), "=r"(r[3]) : "r"(addr));
}
static __device__ __forceinline__ void mma16816(float* c, uint32_t a0, uint32_t a1,
                                                uint32_t a2, uint32_t a3,
                                                uint32_t b0, uint32_t b1) {
    asm volatile("mma.sync.aligned.m16n8k16.row.col.f32.f16.f16.f32 "
                 "{%0,%1,%2,%3}, {%4,%5,%6,%7}, {%8,%9}, {%0,%1,%2,%3};"
                 : "+f"(c[0]), "+f"(c[1]), "+f"(c[2]), "+f"(c[3])
                 : "r"(a0), "r"(a1), "r"(a2), "r"(a3), "r"(b0), "r"(b1));
}
static __device__ __forceinline__ uint32_t packh2(float x, float y) {
    __half2 h = __floats2half2_rn(x, y);
    return *reinterpret_cast<uint32_t*>(&h);
}

// stage a 128n x 64k fp16 B tile (SW128-swizzled, 128B rows) via cp.async
static __device__ __forceinline__ void copy_b_tile(uint32_t sb, int buf, int tid,
                                                   const __half* wp) {
    #pragma unroll
    for (int j = 0; j < 4; j++) {
        int g = tid + j * 256;
        int n = g >> 3, c = g & 7;
        uint32_t off = (uint32_t)(n * 128 + c * 16);
        off ^= (uint32_t)((n & 7) << 4);
        cp16(sb + SM_B + buf * 16384 + off, wp + (size_t)n * IND + c * 8);
    }
}

// ---------- prepass: weights f32 -> f16 ----------
__global__ void dynlin_wconv_kernel(const float* __restrict__ w) {
    size_t i = ((size_t)blockIdx.x * blockDim.x + threadIdx.x) * 4;
    float4 v = *reinterpret_cast<const float4*>(w + i);
    *reinterpret_cast<__half2*>(g_wh + i)     = __floats2half2_rn(v.x, v.y);
    *reinterpret_cast<__half2*>(g_wh + i + 2) = __floats2half2_rn(v.z, v.w);
}

// ---------- main fused kernel ----------
__global__ void __launch_bounds__(256)
dynlin_main_kernel(const float* __restrict__ input,
                   const float* __restrict__ wv,
                   const float* __restrict__ biases,
                   float* __restrict__ out)
{
    extern __shared__ char sm[];
    const uint32_t sb = smem_u32(sm);
    const int tid  = threadIdx.x;
    const int lane = tid & 31;
    const int wid  = tid >> 5;
    const int wm   = wid & 3;          // 4 warp rows  (32 out-rows each)
    const int wn   = wid >> 2;         // 2 warp cols  (64 out-cols each)
    const int col0 = blockIdx.x * TN;
    const int row0 = blockIdx.y * TM;

    // bias tile [8][128] -> SMEM
    {
        int d = tid >> 5, c4 = lane << 2;
        float4 bv = *reinterpret_cast<const float4*>(biases + (size_t)d * OUTD + col0 + c4);
        *reinterpret_cast<float4*>(sm + SM_BIAS + (d * TN + c4) * 4) = bv;
    }

    // per-thread w for its 4 accumulator rows: wr[mt][rs][d]
    float wr[2][2][8];
    #pragma unroll
    for (int mt = 0; mt < 2; mt++)
        #pragma unroll
        for (int rs = 0; rs < 2; rs++) {
            int r = row0 + wm * 32 + mt * 16 + rs * 8 + (lane >> 2);
            float4 w0 = *reinterpret_cast<const float4*>(wv + (size_t)r * DD);
            float4 w1 = *reinterpret_cast<const float4*>(wv + (size_t)r * DD + 4);
            wr[mt][rs][0] = w0.x; wr[mt][rs][1] = w0.y;
            wr[mt][rs][2] = w0.z; wr[mt][rs][3] = w0.w;
            wr[mt][rs][4] = w1.x; wr[mt][rs][5] = w1.y;
            wr[mt][rs][6] = w1.z; wr[mt][rs][7] = w1.w;
        }

    float acc[2][8][4];
    #pragma unroll
    for (int mt = 0; mt < 2; mt++)
        #pragma unroll
        for (int nt = 0; nt < 8; nt++)
            #pragma unroll
            for (int k = 0; k < 4; k++) acc[mt][nt][k] = 0.f;

    // prologue: prefetch B for step 0 (d=0, ic=0) into buf 0
    copy_b_tile(sb, 0, tid, g_wh + (size_t)col0 * IND);
    cp_commit();

    float2 inc[2][4][2][2];   // input cache: [mt][kb][rs][hs], refreshed per ic

    for (int ic = 0; ic < NIC; ic++) {
        const int i0 = ic * KC;
        // refresh input cache (registers only; L1/L2-resident rows)
        #pragma unroll
        for (int mt = 0; mt < 2; mt++)
            #pragma unroll
            for (int rs = 0; rs < 2; rs++) {
                int r = row0 + wm * 32 + mt * 16 + rs * 8 + (lane >> 2);
                const float* ip = input + (size_t)r * IND + i0 + (lane & 3) * 2;
                #pragma unroll
                for (int kb = 0; kb < 4; kb++)
                    #pragma unroll
                    for (int hs = 0; hs < 2; hs++)
                        inc[mt][kb][rs][hs] =
                            *reinterpret_cast<const float2*>(ip + kb * 16 + hs * 8);
            }

        #pragma unroll
        for (int d = 0; d < DD; d++) {
            const int p = d & 1;                  // ic*8 even -> parity depends on d only
            const int s = ic * DD + d;

            if (s + 1 < NSTEPS) {
                const int nd  = (d + 1) & 7;
                const int nic = (d == 7) ? ic + 1 : ic;
                const __half* wp = g_wh + ((size_t)nd * OUTD + col0) * IND + nic * KC;
                copy_b_tile(sb, p ^ 1, tid, wp);
                cp_commit();
                cp_wait1();                       // B(s) resident
            } else {
                cp_wait0();
            }
            __syncthreads();                      // B(s) visible to all warps

            #pragma unroll
            for (int kb = 0; kb < 4; kb++) {
                uint32_t bf[16];
                #pragma unroll
                for (int pr = 0; pr < 4; pr++) {
                    int n = wn * 64 + pr * 16 + (lane & 7) + ((lane >> 4) << 3);
                    uint32_t off = (uint32_t)(n * 128 + kb * 32 + ((lane >> 3) & 1) * 16);
                    off ^= (uint32_t)((n & 7) << 4);
                    ldsm4(bf + pr * 4, sb + SM_B + p * 16384 + off);
                }
                #pragma unroll
                for (int mt = 0; mt < 2; mt++) {
                    const float w0 = wr[mt][0][d], w1 = wr[mt][1][d];
                    uint32_t a0 = packh2(w0 * inc[mt][kb][0][0].x, w0 * inc[mt][kb][0][0].y);
                    uint32_t a1 = packh2(w1 * inc[mt][kb][1][0].x, w1 * inc[mt][kb][1][0].y);
                    uint32_t a2 = packh2(w0 * inc[mt][kb][0][1].x, w0 * inc[mt][kb][0][1].y);
                    uint32_t a3 = packh2(w1 * inc[mt][kb][1][1].x, w1 * inc[mt][kb][1][1].y);
                    #pragma unroll
                    for (int nt = 0; nt < 8; nt++) {
                        int bi = (nt >> 1) * 4 + (nt & 1) * 2;
                        mma16816(acc[mt][nt], a0, a1, a2, a3, bf[bi], bf[bi + 1]);
                    }
                }
            }
            __syncthreads();                      // MMA(s) done before cp overwrites p^1
        }
    }

    // ---- epilogue: out = acc + sum_d w[row,d]*biases[d,col] ----
    #pragma unroll
    for (int nt = 0; nt < 8; nt++) {
        int coff = wn * 64 + nt * 8 + (lane & 3) * 2;
        float2 bv[8];
        #pragma unroll
        for (int d = 0; d < DD; d++)
            bv[d] = *reinterpret_cast<const float2*>(sm + SM_BIAS + (d * TN + coff) * 4);
        #pragma unroll
        for (int mt = 0; mt < 2; mt++)
            #pragma unroll
            for (int rs = 0; rs < 2; rs++) {
                float s0 = 0.f, s1 = 0.f;
                #pragma unroll
                for (int d = 0; d < DD; d++) {
                    s0 = fmaf(wr[mt][rs][d], bv[d].x, s0);
                    s1 = fmaf(wr[mt][rs][d], bv[d].y, s1);
                }
                int r = row0 + wm * 32 + mt * 16 + rs * 8 + (lane >> 2);
                float2 o;
                o.x = acc[mt][nt][rs * 2 + 0] + s0;
                o.y = acc[mt][nt][rs * 2 + 1] + s1;
                *reinterpret_cast<float2*>(out + (size_t)r * OUTD + col0 + coff) = o;
            }
    }
}

extern "C" void kernel_launch(void* const* d_in, const int* in_sizes, int n_in,
                              void* d_out, int out_size) {
    // robust input mapping by element count (dict order kept for the 8.4M pair)
    const float* input = nullptr;
    const float* wv = nullptr;
    const float* weights = nullptr;
    const float* biases = nullptr;
    for (int i = 0; i < n_in; i++) {
        long long sz = in_sizes[i];
        if (sz == (long long)BATCH * DD)           wv = (const float*)d_in[i];
        else if (sz == (long long)DD * OUTD)       biases = (const float*)d_in[i];
        else if (sz == (long long)BATCH * IND) {   // == DD*OUTD*IND too
            if (!input) input = (const float*)d_in[i];
            else        weights = (const float*)d_in[i];
        }
    }
    float* out = (float*)d_out;

    dynlin_wconv_kernel<<<(DD * OUTD * IND) / (256 * 4), 256>>>(weights);

    dim3 grid(OUTD / TN, BATCH / TM);
    dynlin_main_kernel<<<grid, 256, SM_ALLOC>>>(input, wv, biases, out);
}